// round 11
// baseline (speedup 1.0000x reference)
#include <cuda_runtime.h>
#include <cuda_fp16.h>
#include <cstdint>
#include <math.h>

#define BB   64
#define CIN  256
#define HID  256
#define TT   512
#define G4   1024   // 4*HID

// ---------------- scratch (__device__ globals) ------------------------------
__device__ float g_wx[(size_t)TT * BB * G4];      // [t][b][col]  128 MiB
__device__ uint4 g_wA[(size_t)BB * 2 * 16 * 512]; // own-k block
__device__ uint4 g_wB[(size_t)BB * 2 * 16 * 512]; // peer-k block

// column slot lc in [0,512): gate = lc&3 (i,f,g,o), unit j = lc>>2.
__device__ __forceinline__ int gcol(int lc, int half) {
    int g = lc & 3;
    int j = lc >> 2;
    return g * 256 + half * 128 + j;
}

__device__ __forceinline__ float tanh_f(float x) {
    float e = __expf(2.0f * x);
    return 1.0f - __fdividef(2.0f, e + 1.0f);
}
__device__ __forceinline__ float sig_f(float x) {
    return __fdividef(1.0f, 1.0f + __expf(-x));
}

// ---------------- conv: W_hh fp32 -> fp16 blobs ------------------------------
__global__ __launch_bounds__(256) void conv_whh_kernel(const float* __restrict__ Whh) {
    int t    = blockIdx.x * 256 + threadIdx.x;
    int lc   = t & 511;
    int k8   = (t >> 9) & 15;
    int half = (t >> 13) & 1;
    int b    = t >> 14;
    int col  = gcol(lc, half);
    {
        int kg0 = half * 128 + k8 * 8;
        const float* s = Whh + ((size_t)b * HID + kg0) * G4 + col;
        __half hx[8];
        #pragma unroll
        for (int i = 0; i < 8; i++) hx[i] = __float2half(s[(size_t)i * G4]);
        g_wA[t] = *(uint4*)hx;
    }
    {
        int kg0 = (1 - half) * 128 + k8 * 8;
        const float* s = Whh + ((size_t)b * HID + kg0) * G4 + col;
        __half hx[8];
        #pragma unroll
        for (int i = 0; i < 8; i++) hx[i] = __float2half(s[(size_t)i * G4]);
        g_wB[t] = *(uint4*)hx;
    }
}

// ---------------- phase 1: single-kernel HMMA GEMM (R6/R7-proven) -----------
__device__ __forceinline__ void mma16816(float* d, const uint32_t* a, const uint32_t* bf) {
    asm volatile(
        "mma.sync.aligned.m16n8k16.row.col.f32.f16.f16.f32 "
        "{%0,%1,%2,%3}, {%4,%5,%6,%7}, {%8,%9}, {%0,%1,%2,%3};"
        : "+f"(d[0]), "+f"(d[1]), "+f"(d[2]), "+f"(d[3])
        : "r"(a[0]), "r"(a[1]), "r"(a[2]), "r"(a[3]), "r"(bf[0]), "r"(bf[1]));
}

#define LDA 40

__global__ __launch_bounds__(256) void wx_hmma_kernel(
    const float* __restrict__ x,
    const float* __restrict__ Wih,
    const float* __restrict__ bh)
{
    __shared__ __half As[128 * LDA];
    __shared__ __half Bs[128 * LDA];

    const int tid  = threadIdx.x;
    const int m0   = blockIdx.x * 128;
    const int n0   = blockIdx.y * 128;
    const int b    = blockIdx.z;
    const int wid  = tid >> 5, lane = tid & 31;
    const int wm   = (wid & 1) * 64, wn = (wid >> 1) * 32;
    const int g    = lane >> 2, tig = lane & 3;

    float acc[4][4][4];
    #pragma unroll
    for (int i = 0; i < 4; i++)
        #pragma unroll
        for (int j = 0; j < 4; j++)
            #pragma unroll
            for (int r = 0; r < 4; r++) acc[i][j][r] = 0.0f;

    const float* xb = x   + (size_t)b * CIN * TT + m0;
    const float* wb = Wih + (size_t)b * CIN * G4 + n0;

    #pragma unroll 1
    for (int kb = 0; kb < CIN; kb += 32) {
        #pragma unroll
        for (int i = 0; i < 4; i++) {
            int idx = tid + i * 256;
            int kl = idx >> 5, tq = idx & 31;
            float4 v = *(const float4*)(xb + (size_t)(kb + kl) * TT + tq * 4);
            __half* d = As + (tq * 4) * LDA + kl;
            d[0]       = __float2half_rn(v.x);
            d[LDA]     = __float2half_rn(v.y);
            d[2 * LDA] = __float2half_rn(v.z);
            d[3 * LDA] = __float2half_rn(v.w);
        }
        #pragma unroll
        for (int i = 0; i < 4; i++) {
            int idx = tid + i * 256;
            int kl = idx >> 5, nq = idx & 31;
            float4 v = *(const float4*)(wb + (size_t)(kb + kl) * G4 + nq * 4);
            __half* d = Bs + (nq * 4) * LDA + kl;
            d[0]       = __float2half_rn(v.x);
            d[LDA]     = __float2half_rn(v.y);
            d[2 * LDA] = __float2half_rn(v.z);
            d[3 * LDA] = __float2half_rn(v.w);
        }
        __syncthreads();

        #pragma unroll
        for (int ks = 0; ks < 2; ks++) {
            uint32_t a[4][4], bf[4][2];
            #pragma unroll
            for (int mf = 0; mf < 4; mf++) {
                const __half* base = As + (wm + mf * 16 + g) * LDA + ks * 16 + tig * 2;
                a[mf][0] = *(const uint32_t*)(base);
                a[mf][1] = *(const uint32_t*)(base + 8 * LDA);
                a[mf][2] = *(const uint32_t*)(base + 8);
                a[mf][3] = *(const uint32_t*)(base + 8 * LDA + 8);
            }
            #pragma unroll
            for (int nf = 0; nf < 4; nf++) {
                const __half* base = Bs + (wn + nf * 8 + g) * LDA + ks * 16 + tig * 2;
                bf[nf][0] = *(const uint32_t*)(base);
                bf[nf][1] = *(const uint32_t*)(base + 8);
            }
            #pragma unroll
            for (int mf = 0; mf < 4; mf++)
                #pragma unroll
                for (int nf = 0; nf < 4; nf++)
                    mma16816(acc[mf][nf], a[mf], bf[nf]);
        }
        __syncthreads();
    }

    #pragma unroll
    for (int nf = 0; nf < 4; nf++) {
        int col = n0 + wn + nf * 8 + tig * 2;
        float2 bias = *(const float2*)(bh + (size_t)b * G4 + col);
        #pragma unroll
        for (int mf = 0; mf < 4; mf++) {
            int t0 = m0 + wm + mf * 16 + g;
            float2 v0 = { acc[mf][nf][0] + bias.x, acc[mf][nf][1] + bias.y };
            float2 v1 = { acc[mf][nf][2] + bias.x, acc[mf][nf][3] + bias.y };
            *(float2*)(g_wx + ((size_t)t0 * BB + b) * G4 + col) = v0;
            *(float2*)(g_wx + ((size_t)(t0 + 8) * BB + b) * G4 + col) = v1;
        }
    }
}

// ---------------- phase 2: recurrence, 512 thr, quad-gate shfl tail ---------
#define SMEM_W_BYTES  (12 * 512 * 16)                 // 98304
#define SMEM_HS_OFF   SMEM_W_BYTES
#define SMEM_TOTAL_R  (SMEM_HS_OFF + 2 * 128 * 4)     // 99328 B

__global__ void __cluster_dims__(2, 1, 1) __launch_bounds__(512, 1)
lstm_rec_kernel(const float* __restrict__ h0,
                const float* __restrict__ c0,
                float* __restrict__ out)
{
    extern __shared__ char smem[];
    uint4*   w_s  = (uint4*)smem;                     // peer chunks 4..15
    __half2* hs2  = (__half2*)(smem + SMEM_HS_OFF);

    const int tid    = threadIdx.x;                   // 0..511 = column slot
    const int b      = blockIdx.x >> 1;
    const int half   = blockIdx.x & 1;
    const int HALF16 = half * 16;
    const int PEER16 = 16 - HALF16;
    const int r      = tid & 3;       // gate role: 0=i 1=f 2=g 3=o
    const int j      = tid >> 2;      // unit index (local, 0..127)

    // weight residency: own 16 chunks in regs, peer 4 regs + 12 SMEM
    uint4 wregA[16], wregP[4];
    const uint4* gwa = g_wA + ((size_t)(b * 2 + half) << 13);
    #pragma unroll
    for (int a = 0; a < 16; a++) wregA[a] = gwa[a * 512 + tid];
    const uint4* gwb = g_wB + ((size_t)(b * 2 + half) << 13);
    #pragma unroll
    for (int a = 0; a < 4; a++) wregP[a] = gwb[a * 512 + tid];
    #pragma unroll
    for (int a = 4; a < 16; a++) w_s[(a - 4) * 512 + tid] = gwb[a * 512 + tid];

    // init state: all 4 quad threads hold c redundantly
    float c = c0[b * HID + half * 128 + j];
    if (tid < 128)
        hs2[tid] = __floats2half2_rn(h0[b * HID + 2 * tid],
                                     h0[b * HID + 2 * tid + 1]);
    __syncthreads();
    asm volatile("barrier.cluster.arrive.aligned;\n\t"
                 "barrier.cluster.wait.aligned;" ::: "memory");

    const uint32_t hsAddrBase = (uint32_t)__cvta_generic_to_shared(hs2);
    const uint32_t peerRank   = (uint32_t)(half ^ 1);
    uint32_t rHsBase;
    asm volatile("mapa.shared::cluster.u32 %0, %1, %2;"
                 : "=r"(rHsBase) : "r"(hsAddrBase), "r"(peerRank));

    const int colA = gcol(tid, half);
    const float* wx_ptr = g_wx + (size_t)b * G4 + colA;

    float wx = __ldg(wx_ptr);
    const __half2 hz = __float2half2_rn(0.0f);

    #pragma unroll 1
    for (int t = 0; t < TT; t++) {
        const int p = t & 1;

        float nx = wx;
        if (t + 1 < TT) nx = __ldg(wx_ptr + (size_t)(t + 1) * (BB * G4));

        float acc = wx;
        const __half2* hsp = hs2 + p * 128;

        // ---- phase A: own-k block (register weights, local h) ----
        #pragma unroll
        for (int q = 0; q < 4; q++) {
            __half2 s = hz;
            #pragma unroll
            for (int i = 0; i < 4; i++) {
                int a  = q * 4 + i;
                int k8 = HALF16 + a;
                uint4 hv = *(const uint4*)(hsp + k8 * 4);
                uint4 wa = wregA[a];
                s = __hfma2(*(__half2*)&hv.x, *(__half2*)&wa.x, s);
                s = __hfma2(*(__half2*)&hv.y, *(__half2*)&wa.y, s);
                s = __hfma2(*(__half2*)&hv.z, *(__half2*)&wa.z, s);
                s = __hfma2(*(__half2*)&hv.w, *(__half2*)&wa.w, s);
            }
            float2 f = __half22float2(s);
            acc += f.x + f.y;
        }

        // ---- wait for peer h of this step (split cluster barrier) ----
        if (t) asm volatile("barrier.cluster.wait.aligned;" ::: "memory");

        // ---- phase B: peer-k block (4 reg chunks + 12 SMEM chunks) ----
        #pragma unroll
        for (int q = 0; q < 4; q++) {
            __half2 s = hz;
            #pragma unroll
            for (int i = 0; i < 4; i++) {
                int a  = q * 4 + i;
                int k8 = PEER16 + a;
                uint4 hv = *(const uint4*)(hsp + k8 * 4);
                uint4 wa = (a < 4) ? wregP[a] : w_s[(a - 4) * 512 + tid];
                s = __hfma2(*(__half2*)&hv.x, *(__half2*)&wa.x, s);
                s = __hfma2(*(__half2*)&hv.y, *(__half2*)&wa.y, s);
                s = __hfma2(*(__half2*)&hv.z, *(__half2*)&wa.z, s);
                s = __hfma2(*(__half2*)&hv.w, *(__half2*)&wa.w, s);
            }
            float2 f = __half22float2(s);
            acc += f.x + f.y;
        }

        // ---- quad-gate tail: one tanh, gather 4 gates via shfl -------------
        float ga = tanh_f(acc);                              // my gate
        float v1 = __shfl_xor_sync(0xffffffffu, ga, 1);      // gate r^1
        float v2 = __shfl_xor_sync(0xffffffffu, ga, 2);      // gate r^2
        float v3 = __shfl_xor_sync(0xffffffffu, v1, 2);      // gate r^3

        // gate q value = (q==r)?ga : (q==r^1)?v1 : (q==r^2)?v2 : v3
        float ti = (r == 0) ? ga : (r == 1) ? v1 : (r == 2) ? v2 : v3;
        float tf = (r == 1) ? ga : (r == 0) ? v1 : (r == 3) ? v2 : v3;
        float tg = (r == 2) ? ga : (r == 3) ? v1 : (r == 0) ? v2 : v3;
        float to = (r == 3) ? ga : (r == 2) ? v1 : (r == 1) ? v2 : v3;

        c = c * sig_f(tf) + sig_f(ti) * tanh_f(tg);
        float hn = sig_f(to) * tanh_f(c);

        if (r == 3)
            out[((size_t)(b * HID + half * 128 + j)) * TT + t] = hn;

        // pack h pair: tid%8==0 packs units (j, j+1); hn(j+1) at tid+4
        float ho = __shfl_xor_sync(0xffffffffu, hn, 4);
        if ((tid & 7) == 0) {
            __half2 hp = __floats2half2_rn(hn, ho);
            int k2 = half * 64 + (tid >> 3);
            uint32_t off = (uint32_t)(((p ^ 1) * 128 + k2) * 4);
            hs2[(p ^ 1) * 128 + k2] = hp;                    // local copy
            if (t + 1 < TT)
                asm volatile("st.shared::cluster.u32 [%0], %1;"
                             :: "r"(rHsBase + off), "r"(*(uint32_t*)&hp) : "memory");
        }
        __syncthreads();
        asm volatile("barrier.cluster.arrive.aligned;" ::: "memory");

        wx = nx;
    }
    asm volatile("barrier.cluster.wait.aligned;" ::: "memory");

    if (r == 3)
        out[(size_t)BB * HID * TT + b * HID + half * 128 + j] = c;
}

// ---------------- launch ------------------------------------------------------
extern "C" void kernel_launch(void* const* d_in, const int* in_sizes, int n_in,
                              void* d_out, int out_size) {
    const float* x   = (const float*)d_in[0];
    const float* h0  = (const float*)d_in[1];
    const float* c0  = (const float*)d_in[2];
    const float* Wih = (const float*)d_in[3];
    const float* Whh = (const float*)d_in[4];
    const float* bh  = (const float*)d_in[5];
    float* out = (float*)d_out;

    cudaFuncSetAttribute(lstm_rec_kernel,
                         cudaFuncAttributeMaxDynamicSharedMemorySize, SMEM_TOTAL_R);

    conv_whh_kernel<<<(BB * 2 * 16 * 512) / 256, 256>>>(Whh);

    wx_hmma_kernel<<<dim3(TT / 128, G4 / 128, BB), 256>>>(x, Wih, bh);

    lstm_rec_kernel<<<2 * BB, 512, SMEM_TOTAL_R>>>(h0, c0, out);

    (void)in_sizes; (void)n_in; (void)out_size;
}

// round 12
// speedup vs baseline: 1.2078x; 1.2078x over previous
#include <cuda_runtime.h>
#include <cuda_fp16.h>
#include <cstdint>
#include <math.h>

#define BB   64
#define CIN  256
#define HID  256
#define TT   512
#define G4   1024   // 4*HID

// ---------------- scratch (__device__ globals) ------------------------------
__device__ float g_wx[(size_t)TT * BB * G4];      // [t][b][col]  128 MiB
__device__ uint4 g_wA[(size_t)BB * 2 * 16 * 512]; // own-k block
__device__ uint4 g_wB[(size_t)BB * 2 * 16 * 512]; // peer-k block

// column slot lc in [0,512) -> global gate column (R10 map).
// th = lc&255: unit j = th>>1, role = th&1 (0:(i,g), 1:(f,o)); sel = lc>>8.
__device__ __forceinline__ int gcol(int lc, int half) {
    int th   = lc & 255;
    int sel  = lc >> 8;
    int role = th & 1;
    int j    = th >> 1;
    int g    = sel * 2 + role;
    return g * 256 + half * 128 + j;
}

__device__ __forceinline__ float tanh_f(float x) {
    float e = __expf(2.0f * x);
    return 1.0f - __fdividef(2.0f, e + 1.0f);
}
__device__ __forceinline__ float sig_f(float x) {
    return __fdividef(1.0f, 1.0f + __expf(-x));
}

// ---------------- conv: W_hh fp32 -> fp16 blobs ------------------------------
__global__ __launch_bounds__(256) void conv_whh_kernel(const float* __restrict__ Whh) {
    int t    = blockIdx.x * 256 + threadIdx.x;
    int lc   = t & 511;
    int k8   = (t >> 9) & 15;
    int half = (t >> 13) & 1;
    int b    = t >> 14;
    int col  = gcol(lc, half);
    {
        int kg0 = half * 128 + k8 * 8;
        const float* s = Whh + ((size_t)b * HID + kg0) * G4 + col;
        __half hx[8];
        #pragma unroll
        for (int i = 0; i < 8; i++) hx[i] = __float2half(s[(size_t)i * G4]);
        g_wA[t] = *(uint4*)hx;
    }
    {
        int kg0 = (1 - half) * 128 + k8 * 8;
        const float* s = Whh + ((size_t)b * HID + kg0) * G4 + col;
        __half hx[8];
        #pragma unroll
        for (int i = 0; i < 8; i++) hx[i] = __float2half(s[(size_t)i * G4]);
        g_wB[t] = *(uint4*)hx;
    }
}

// ---------------- phase 1: single-kernel HMMA GEMM (proven) -----------------
__device__ __forceinline__ void mma16816(float* d, const uint32_t* a, const uint32_t* bf) {
    asm volatile(
        "mma.sync.aligned.m16n8k16.row.col.f32.f16.f16.f32 "
        "{%0,%1,%2,%3}, {%4,%5,%6,%7}, {%8,%9}, {%0,%1,%2,%3};"
        : "+f"(d[0]), "+f"(d[1]), "+f"(d[2]), "+f"(d[3])
        : "r"(a[0]), "r"(a[1]), "r"(a[2]), "r"(a[3]), "r"(bf[0]), "r"(bf[1]));
}

#define LDA 40

__global__ __launch_bounds__(256) void wx_hmma_kernel(
    const float* __restrict__ x,
    const float* __restrict__ Wih,
    const float* __restrict__ bh)
{
    __shared__ __half As[128 * LDA];
    __shared__ __half Bs[128 * LDA];

    const int tid  = threadIdx.x;
    const int m0   = blockIdx.x * 128;
    const int n0   = blockIdx.y * 128;
    const int b    = blockIdx.z;
    const int wid  = tid >> 5, lane = tid & 31;
    const int wm   = (wid & 1) * 64, wn = (wid >> 1) * 32;
    const int g    = lane >> 2, tig = lane & 3;

    float acc[4][4][4];
    #pragma unroll
    for (int i = 0; i < 4; i++)
        #pragma unroll
        for (int j = 0; j < 4; j++)
            #pragma unroll
            for (int r = 0; r < 4; r++) acc[i][j][r] = 0.0f;

    const float* xb = x   + (size_t)b * CIN * TT + m0;
    const float* wb = Wih + (size_t)b * CIN * G4 + n0;

    #pragma unroll 1
    for (int kb = 0; kb < CIN; kb += 32) {
        #pragma unroll
        for (int i = 0; i < 4; i++) {
            int idx = tid + i * 256;
            int kl = idx >> 5, tq = idx & 31;
            float4 v = *(const float4*)(xb + (size_t)(kb + kl) * TT + tq * 4);
            __half* d = As + (tq * 4) * LDA + kl;
            d[0]       = __float2half_rn(v.x);
            d[LDA]     = __float2half_rn(v.y);
            d[2 * LDA] = __float2half_rn(v.z);
            d[3 * LDA] = __float2half_rn(v.w);
        }
        #pragma unroll
        for (int i = 0; i < 4; i++) {
            int idx = tid + i * 256;
            int kl = idx >> 5, nq = idx & 31;
            float4 v = *(const float4*)(wb + (size_t)(kb + kl) * G4 + nq * 4);
            __half* d = Bs + (nq * 4) * LDA + kl;
            d[0]       = __float2half_rn(v.x);
            d[LDA]     = __float2half_rn(v.y);
            d[2 * LDA] = __float2half_rn(v.z);
            d[3 * LDA] = __float2half_rn(v.w);
        }
        __syncthreads();

        #pragma unroll
        for (int ks = 0; ks < 2; ks++) {
            uint32_t a[4][4], bf[4][2];
            #pragma unroll
            for (int mf = 0; mf < 4; mf++) {
                const __half* base = As + (wm + mf * 16 + g) * LDA + ks * 16 + tig * 2;
                a[mf][0] = *(const uint32_t*)(base);
                a[mf][1] = *(const uint32_t*)(base + 8 * LDA);
                a[mf][2] = *(const uint32_t*)(base + 8);
                a[mf][3] = *(const uint32_t*)(base + 8 * LDA + 8);
            }
            #pragma unroll
            for (int nf = 0; nf < 4; nf++) {
                const __half* base = Bs + (wn + nf * 8 + g) * LDA + ks * 16 + tig * 2;
                bf[nf][0] = *(const uint32_t*)(base);
                bf[nf][1] = *(const uint32_t*)(base + 8);
            }
            #pragma unroll
            for (int mf = 0; mf < 4; mf++)
                #pragma unroll
                for (int nf = 0; nf < 4; nf++)
                    mma16816(acc[mf][nf], a[mf], bf[nf]);
        }
        __syncthreads();
    }

    #pragma unroll
    for (int nf = 0; nf < 4; nf++) {
        int col = n0 + wn + nf * 8 + tig * 2;
        float2 bias = *(const float2*)(bh + (size_t)b * G4 + col);
        #pragma unroll
        for (int mf = 0; mf < 4; mf++) {
            int t0 = m0 + wm + mf * 16 + g;
            float2 v0 = { acc[mf][nf][0] + bias.x, acc[mf][nf][1] + bias.y };
            float2 v1 = { acc[mf][nf][2] + bias.x, acc[mf][nf][3] + bias.y };
            *(float2*)(g_wx + ((size_t)t0 * BB + b) * G4 + col) = v0;
            *(float2*)(g_wx + ((size_t)(t0 + 8) * BB + b) * G4 + col) = v1;
        }
    }
}

// ---------------- phase 2: recurrence (R10 base + flag handshake) -----------
#define SMEM_W_BYTES  (8 * 512 * 16)                  // 65536
#define SMEM_HS_OFF   SMEM_W_BYTES
#define SMEM_FLAG_OFF (SMEM_HS_OFF + 2 * 128 * 4)
#define SMEM_TOTAL_R  (SMEM_FLAG_OFF + 16)            // 66576 B

__global__ void __cluster_dims__(2, 1, 1) __launch_bounds__(256, 1)
lstm_rec_kernel(const float* __restrict__ h0,
                const float* __restrict__ c0,
                float* __restrict__ out)
{
    extern __shared__ char smem[];
    uint4*   w_s  = (uint4*)smem;                     // peer chunks 8..15
    __half2* hs2  = (__half2*)(smem + SMEM_HS_OFF);

    const int tid    = threadIdx.x;
    const int b      = blockIdx.x >> 1;
    const int half   = blockIdx.x & 1;
    const int HALF16 = half * 16;
    const int PEER16 = 16 - HALF16;
    const int role   = tid & 1;       // 0:(i,g)  1:(f,o)
    const int j      = tid >> 1;      // unit index (local, 0..127)

    // weight residency (R7/R10 structure)
    uint4 wregA[16], wregB[16], wregPA[8], wregPB[8];
    const uint4* gwa = g_wA + ((size_t)(b * 2 + half) << 13);
    #pragma unroll
    for (int a = 0; a < 16; a++) {
        wregA[a] = gwa[a * 512 + tid];
        wregB[a] = gwa[a * 512 + tid + 256];
    }
    const uint4* gwb = g_wB + ((size_t)(b * 2 + half) << 13);
    #pragma unroll
    for (int a = 0; a < 8; a++) {
        wregPA[a] = gwb[a * 512 + tid];
        wregPB[a] = gwb[a * 512 + tid + 256];
    }
    #pragma unroll
    for (int a = 8; a < 16; a++) {
        w_s[(a - 8) * 512 + tid]       = gwb[a * 512 + tid];
        w_s[(a - 8) * 512 + tid + 256] = gwb[a * 512 + tid + 256];
    }

    // init state: both pair threads hold c redundantly
    float c = c0[b * HID + half * 128 + j];
    if (tid < 128)
        hs2[tid] = __floats2half2_rn(h0[b * HID + 2 * tid],
                                     h0[b * HID + 2 * tid + 1]);
    if (tid == 0)
        *(volatile uint32_t*)(smem + SMEM_FLAG_OFF) = 0;   // flag: h(t) delivered count
    __syncthreads();
    asm volatile("barrier.cluster.arrive.aligned;\n\t"
                 "barrier.cluster.wait.aligned;" ::: "memory");

    const uint32_t smemBase   = (uint32_t)__cvta_generic_to_shared(smem);
    const uint32_t hsAddrBase = smemBase + SMEM_HS_OFF;
    const uint32_t flagAddr   = smemBase + SMEM_FLAG_OFF;
    const uint32_t peerRank   = (uint32_t)(half ^ 1);
    uint32_t rHsBase, rFlag;
    asm volatile("mapa.shared::cluster.u32 %0, %1, %2;"
                 : "=r"(rHsBase) : "r"(hsAddrBase), "r"(peerRank));
    asm volatile("mapa.shared::cluster.u32 %0, %1, %2;"
                 : "=r"(rFlag) : "r"(flagAddr), "r"(peerRank));

    const int colA = gcol(tid, half);
    const float* wxA_ptr = g_wx + (size_t)b * G4 + colA;
    const float* wxB_ptr = wxA_ptr + 512;

    float wxA = __ldg(wxA_ptr);
    float wxB = __ldg(wxB_ptr);
    const __half2 hz = __float2half2_rn(0.0f);

    #pragma unroll 1
    for (int t = 0; t < TT; t++) {
        const int p = t & 1;

        float nxA = wxA, nxB = wxB;
        if (t + 1 < TT) {
            size_t off = (size_t)(t + 1) * (BB * G4);
            nxA = __ldg(wxA_ptr + off);
            nxB = __ldg(wxB_ptr + off);
        }

        float accA = wxA, accB = wxB;
        const __half2* hsp = hs2 + p * 128;

        // ---- phase A: own-k block (register weights, local h) ----
        #pragma unroll
        for (int q = 0; q < 4; q++) {
            __half2 sA = hz, sB = hz;
            #pragma unroll
            for (int i = 0; i < 4; i++) {
                int a  = q * 4 + i;
                int k8 = HALF16 + a;
                uint4 hv = *(const uint4*)(hsp + k8 * 4);
                __half2 h01 = *(__half2*)&hv.x, h23 = *(__half2*)&hv.y;
                __half2 h45 = *(__half2*)&hv.z, h67 = *(__half2*)&hv.w;
                uint4 wa = wregA[a], wb = wregB[a];
                sA = __hfma2(h01, *(__half2*)&wa.x, sA);
                sA = __hfma2(h23, *(__half2*)&wa.y, sA);
                sA = __hfma2(h45, *(__half2*)&wa.z, sA);
                sA = __hfma2(h67, *(__half2*)&wa.w, sA);
                sB = __hfma2(h01, *(__half2*)&wb.x, sB);
                sB = __hfma2(h23, *(__half2*)&wb.y, sB);
                sB = __hfma2(h45, *(__half2*)&wb.z, sB);
                sB = __hfma2(h67, *(__half2*)&wb.w, sB);
            }
            float2 fa = __half22float2(sA); accA += fa.x + fa.y;
            float2 fb = __half22float2(sB); accB += fb.x + fb.y;
        }

        // ---- wait for peer h of this step (flag spin, fast path ~30-60cyc) --
        if (t) {
            uint32_t v;
            do {
                asm volatile("ld.acquire.cluster.shared::cta.b32 %0, [%1];"
                             : "=r"(v) : "r"(flagAddr) : "memory");
            } while ((int)v < t);
        }

        // ---- phase B: peer-k block (8 reg chunks + 8 SMEM chunks) ----
        #pragma unroll
        for (int q = 0; q < 4; q++) {
            __half2 sA = hz, sB = hz;
            #pragma unroll
            for (int i = 0; i < 4; i++) {
                int bi = q * 4 + i;
                int k8 = PEER16 + bi;
                uint4 hv = *(const uint4*)(hsp + k8 * 4);
                __half2 h01 = *(__half2*)&hv.x, h23 = *(__half2*)&hv.y;
                __half2 h45 = *(__half2*)&hv.z, h67 = *(__half2*)&hv.w;
                uint4 wa, wb;
                if (bi < 8) { wa = wregPA[bi]; wb = wregPB[bi]; }
                else {
                    wa = w_s[(bi - 8) * 512 + tid];
                    wb = w_s[(bi - 8) * 512 + tid + 256];
                }
                sA = __hfma2(h01, *(__half2*)&wa.x, sA);
                sA = __hfma2(h23, *(__half2*)&wa.y, sA);
                sA = __hfma2(h45, *(__half2*)&wa.z, sA);
                sA = __hfma2(h67, *(__half2*)&wa.w, sA);
                sB = __hfma2(h01, *(__half2*)&wb.x, sB);
                sB = __hfma2(h23, *(__half2*)&wb.y, sB);
                sB = __hfma2(h45, *(__half2*)&wb.z, sB);
                sB = __hfma2(h67, *(__half2*)&wb.w, sB);
            }
            float2 fa = __half22float2(sA); accA += fa.x + fa.y;
            float2 fb = __half22float2(sB); accB += fb.x + fb.y;
        }

        // ---- branch-free redundant activation tail (R10) ----
        float ga = tanh_f(accA);
        float gb = tanh_f(accB);
        float gax = __shfl_xor_sync(0xffffffffu, ga, 1);
        float gbx = __shfl_xor_sync(0xffffffffu, gb, 1);

        float ti = role ? gax : ga;
        float tf = role ? ga  : gax;
        float tg = role ? gbx : gb;
        float to = role ? gb  : gbx;

        c = c * sig_f(tf) + sig_f(ti) * tanh_f(tg);
        float hn = sig_f(to) * tanh_f(c);

        if (role)
            out[((size_t)(b * HID + half * 128 + j)) * TT + t] = hn;

        // pack h pair: tid%4==0 packs units (j, j+1)
        float ho = __shfl_xor_sync(0xffffffffu, hn, 2);
        if ((tid & 3) == 0) {
            __half2 hp = __floats2half2_rn(hn, ho);
            int k2 = half * 64 + (tid >> 2);
            uint32_t off = (uint32_t)(((p ^ 1) * 128 + k2) * 4);
            hs2[(p ^ 1) * 128 + k2] = hp;                    // local copy
            if (t + 1 < TT)
                asm volatile("st.shared::cluster.u32 [%0], %1;"
                             :: "r"(rHsBase + off), "r"(*(uint32_t*)&hp) : "memory");
        }
        __syncthreads();   // all local reads of buffer p done; h stores issued

        // single release-signal to peer: h(t+1) delivered, buffer p free
        if (tid == 0 && t + 1 < TT) {
            asm volatile("fence.acq_rel.cluster;" ::: "memory");
            asm volatile("st.relaxed.cluster.shared::cluster.b32 [%0], %1;"
                         :: "r"(rFlag), "r"(t + 1) : "memory");
        }

        wxA = nxA; wxB = nxB;
    }

    if (role)
        out[(size_t)BB * HID * TT + b * HID + half * 128 + j] = c;

    // exit safety: peer DSMEM stores targeting this CTA must complete
    asm volatile("barrier.cluster.arrive.aligned;\n\t"
                 "barrier.cluster.wait.aligned;" ::: "memory");
}

// ---------------- launch ------------------------------------------------------
extern "C" void kernel_launch(void* const* d_in, const int* in_sizes, int n_in,
                              void* d_out, int out_size) {
    const float* x   = (const float*)d_in[0];
    const float* h0  = (const float*)d_in[1];
    const float* c0  = (const float*)d_in[2];
    const float* Wih = (const float*)d_in[3];
    const float* Whh = (const float*)d_in[4];
    const float* bh  = (const float*)d_in[5];
    float* out = (float*)d_out;

    cudaFuncSetAttribute(lstm_rec_kernel,
                         cudaFuncAttributeMaxDynamicSharedMemorySize, SMEM_TOTAL_R);

    conv_whh_kernel<<<(BB * 2 * 16 * 512) / 256, 256>>>(Whh);

    wx_hmma_kernel<<<dim3(TT / 128, G4 / 128, BB), 256>>>(x, Wih, bh);

    lstm_rec_kernel<<<2 * BB, 256, SMEM_TOTAL_R>>>(h0, c0, out);

    (void)in_sizes; (void)n_in; (void)out_size;
}

// round 13
// speedup vs baseline: 1.2167x; 1.0074x over previous
#include <cuda_runtime.h>
#include <cuda_fp16.h>
#include <cstdint>
#include <math.h>

#define BB   64
#define CIN  256
#define HID  256
#define TT   512
#define G4   1024   // 4*HID

// ---------------- scratch (__device__ globals) ------------------------------
__device__ float g_wx[(size_t)TT * BB * G4];      // [t][b][col]  128 MiB
__device__ uint4 g_wA[(size_t)BB * 2 * 16 * 512]; // own-k block
__device__ uint4 g_wB[(size_t)BB * 2 * 16 * 512]; // peer-k block

// column slot lc in [0,512) -> global gate column (R10/R12 map).
__device__ __forceinline__ int gcol(int lc, int half) {
    int th   = lc & 255;
    int sel  = lc >> 8;
    int role = th & 1;
    int j    = th >> 1;
    int g    = sel * 2 + role;
    return g * 256 + half * 128 + j;
}

__device__ __forceinline__ float tanh_f(float x) {
    float e = __expf(2.0f * x);
    return 1.0f - __fdividef(2.0f, e + 1.0f);
}
__device__ __forceinline__ float sig_f(float x) {
    return __fdividef(1.0f, 1.0f + __expf(-x));
}

// ---------------- conv: W_hh fp32 -> fp16 blobs ------------------------------
__global__ __launch_bounds__(256) void conv_whh_kernel(const float* __restrict__ Whh) {
    int t    = blockIdx.x * 256 + threadIdx.x;
    int lc   = t & 511;
    int k8   = (t >> 9) & 15;
    int half = (t >> 13) & 1;
    int b    = t >> 14;
    int col  = gcol(lc, half);
    {
        int kg0 = half * 128 + k8 * 8;
        const float* s = Whh + ((size_t)b * HID + kg0) * G4 + col;
        __half hx[8];
        #pragma unroll
        for (int i = 0; i < 8; i++) hx[i] = __float2half(s[(size_t)i * G4]);
        g_wA[t] = *(uint4*)hx;
    }
    {
        int kg0 = (1 - half) * 128 + k8 * 8;
        const float* s = Whh + ((size_t)b * HID + kg0) * G4 + col;
        __half hx[8];
        #pragma unroll
        for (int i = 0; i < 8; i++) hx[i] = __float2half(s[(size_t)i * G4]);
        g_wB[t] = *(uint4*)hx;
    }
}

// ---------------- phase 1: HMMA GEMM, double-buffered staging ---------------
__device__ __forceinline__ void mma16816(float* d, const uint32_t* a, const uint32_t* bf) {
    asm volatile(
        "mma.sync.aligned.m16n8k16.row.col.f32.f16.f16.f32 "
        "{%0,%1,%2,%3}, {%4,%5,%6,%7}, {%8,%9}, {%0,%1,%2,%3};"
        : "+f"(d[0]), "+f"(d[1]), "+f"(d[2]), "+f"(d[3])
        : "r"(a[0]), "r"(a[1]), "r"(a[2]), "r"(a[3]), "r"(bf[0]), "r"(bf[1]));
}

#define LDA 40

__global__ __launch_bounds__(256) void wx_hmma_kernel(
    const float* __restrict__ x,
    const float* __restrict__ Wih,
    const float* __restrict__ bh)
{
    __shared__ __half As[2][128 * LDA];
    __shared__ __half Bs[2][128 * LDA];

    const int tid  = threadIdx.x;
    const int m0   = blockIdx.x * 128;
    const int n0   = blockIdx.y * 128;
    const int b    = blockIdx.z;
    const int wid  = tid >> 5, lane = tid & 31;
    const int wm   = (wid & 1) * 64, wn = (wid >> 1) * 32;
    const int g    = lane >> 2, tig = lane & 3;

    float acc[4][4][4];
    #pragma unroll
    for (int i = 0; i < 4; i++)
        #pragma unroll
        for (int j = 0; j < 4; j++)
            #pragma unroll
            for (int r = 0; r < 4; r++) acc[i][j][r] = 0.0f;

    const float* xb = x   + (size_t)b * CIN * TT + m0;
    const float* wb = Wih + (size_t)b * CIN * G4 + n0;

    auto load_stage = [&](int kb, int s) {
        #pragma unroll
        for (int i = 0; i < 4; i++) {
            int idx = tid + i * 256;
            int kl = idx >> 5, tq = idx & 31;
            float4 v = *(const float4*)(xb + (size_t)(kb + kl) * TT + tq * 4);
            __half* d = As[s] + (tq * 4) * LDA + kl;
            d[0]       = __float2half_rn(v.x);
            d[LDA]     = __float2half_rn(v.y);
            d[2 * LDA] = __float2half_rn(v.z);
            d[3 * LDA] = __float2half_rn(v.w);
        }
        #pragma unroll
        for (int i = 0; i < 4; i++) {
            int idx = tid + i * 256;
            int kl = idx >> 5, nq = idx & 31;
            float4 v = *(const float4*)(wb + (size_t)(kb + kl) * G4 + nq * 4);
            __half* d = Bs[s] + (nq * 4) * LDA + kl;
            d[0]       = __float2half_rn(v.x);
            d[LDA]     = __float2half_rn(v.y);
            d[2 * LDA] = __float2half_rn(v.z);
            d[3 * LDA] = __float2half_rn(v.w);
        }
    };

    load_stage(0, 0);
    __syncthreads();

    #pragma unroll 1
    for (int it = 0; it < 8; it++) {
        const int s = it & 1;
        if (it < 7) load_stage((it + 1) * 32, s ^ 1);   // overlap with mma

        #pragma unroll
        for (int ks = 0; ks < 2; ks++) {
            uint32_t a[4][4], bf[4][2];
            #pragma unroll
            for (int mf = 0; mf < 4; mf++) {
                const __half* base = As[s] + (wm + mf * 16 + g) * LDA + ks * 16 + tig * 2;
                a[mf][0] = *(const uint32_t*)(base);
                a[mf][1] = *(const uint32_t*)(base + 8 * LDA);
                a[mf][2] = *(const uint32_t*)(base + 8);
                a[mf][3] = *(const uint32_t*)(base + 8 * LDA + 8);
            }
            #pragma unroll
            for (int nf = 0; nf < 4; nf++) {
                const __half* base = Bs[s] + (wn + nf * 8 + g) * LDA + ks * 16 + tig * 2;
                bf[nf][0] = *(const uint32_t*)(base);
                bf[nf][1] = *(const uint32_t*)(base + 8);
            }
            #pragma unroll
            for (int mf = 0; mf < 4; mf++)
                #pragma unroll
                for (int nf = 0; nf < 4; nf++)
                    mma16816(acc[mf][nf], a[mf], bf[nf]);
        }
        __syncthreads();
    }

    #pragma unroll
    for (int nf = 0; nf < 4; nf++) {
        int col = n0 + wn + nf * 8 + tig * 2;
        float2 bias = *(const float2*)(bh + (size_t)b * G4 + col);
        #pragma unroll
        for (int mf = 0; mf < 4; mf++) {
            int t0 = m0 + wm + mf * 16 + g;
            float2 v0 = { acc[mf][nf][0] + bias.x, acc[mf][nf][1] + bias.y };
            float2 v1 = { acc[mf][nf][2] + bias.x, acc[mf][nf][3] + bias.y };
            *(float2*)(g_wx + ((size_t)t0 * BB + b) * G4 + col) = v0;
            *(float2*)(g_wx + ((size_t)(t0 + 8) * BB + b) * G4 + col) = v1;
        }
    }
}

// ---------------- phase 2: recurrence (R12 + 8-chunk half2 groups) ----------
#define SMEM_W_BYTES  (8 * 512 * 16)                  // 65536
#define SMEM_HS_OFF   SMEM_W_BYTES
#define SMEM_FLAG_OFF (SMEM_HS_OFF + 2 * 128 * 4)
#define SMEM_TOTAL_R  (SMEM_FLAG_OFF + 16)            // 66576 B

__global__ void __cluster_dims__(2, 1, 1) __launch_bounds__(256, 1)
lstm_rec_kernel(const float* __restrict__ h0,
                const float* __restrict__ c0,
                float* __restrict__ out)
{
    extern __shared__ char smem[];
    uint4*   w_s  = (uint4*)smem;                     // peer chunks 8..15
    __half2* hs2  = (__half2*)(smem + SMEM_HS_OFF);

    const int tid    = threadIdx.x;
    const int b      = blockIdx.x >> 1;
    const int half   = blockIdx.x & 1;
    const int HALF16 = half * 16;
    const int PEER16 = 16 - HALF16;
    const int role   = tid & 1;       // 0:(i,g)  1:(f,o)
    const int j      = tid >> 1;      // unit index (local, 0..127)

    // weight residency
    uint4 wregA[16], wregB[16], wregPA[8], wregPB[8];
    const uint4* gwa = g_wA + ((size_t)(b * 2 + half) << 13);
    #pragma unroll
    for (int a = 0; a < 16; a++) {
        wregA[a] = gwa[a * 512 + tid];
        wregB[a] = gwa[a * 512 + tid + 256];
    }
    const uint4* gwb = g_wB + ((size_t)(b * 2 + half) << 13);
    #pragma unroll
    for (int a = 0; a < 8; a++) {
        wregPA[a] = gwb[a * 512 + tid];
        wregPB[a] = gwb[a * 512 + tid + 256];
    }
    #pragma unroll
    for (int a = 8; a < 16; a++) {
        w_s[(a - 8) * 512 + tid]       = gwb[a * 512 + tid];
        w_s[(a - 8) * 512 + tid + 256] = gwb[a * 512 + tid + 256];
    }

    // init state
    float c = c0[b * HID + half * 128 + j];
    if (tid < 128)
        hs2[tid] = __floats2half2_rn(h0[b * HID + 2 * tid],
                                     h0[b * HID + 2 * tid + 1]);
    if (tid == 0)
        *(volatile uint32_t*)(smem + SMEM_FLAG_OFF) = 0;
    __syncthreads();
    asm volatile("barrier.cluster.arrive.aligned;\n\t"
                 "barrier.cluster.wait.aligned;" ::: "memory");

    const uint32_t smemBase   = (uint32_t)__cvta_generic_to_shared(smem);
    const uint32_t hsAddrBase = smemBase + SMEM_HS_OFF;
    const uint32_t flagAddr   = smemBase + SMEM_FLAG_OFF;
    const uint32_t peerRank   = (uint32_t)(half ^ 1);
    uint32_t rHsBase, rFlag;
    asm volatile("mapa.shared::cluster.u32 %0, %1, %2;"
                 : "=r"(rHsBase) : "r"(hsAddrBase), "r"(peerRank));
    asm volatile("mapa.shared::cluster.u32 %0, %1, %2;"
                 : "=r"(rFlag) : "r"(flagAddr), "r"(peerRank));

    const int colA = gcol(tid, half);
    const float* wxA_ptr = g_wx + (size_t)b * G4 + colA;
    const float* wxB_ptr = wxA_ptr + 512;

    float wxA = __ldg(wxA_ptr);
    float wxB = __ldg(wxB_ptr);
    const __half2 hz = __float2half2_rn(0.0f);

    #pragma unroll 1
    for (int t = 0; t < TT; t++) {
        const int p = t & 1;

        float nxA = wxA, nxB = wxB;
        if (t + 1 < TT) {
            size_t off = (size_t)(t + 1) * (BB * G4);
            nxA = __ldg(wxA_ptr + off);
            nxB = __ldg(wxB_ptr + off);
        }

        float accA = wxA, accB = wxB;
        const __half2* hsp = hs2 + p * 128;

        // ---- phase A: own-k block, 8-chunk half2 groups ----
        #pragma unroll
        for (int q = 0; q < 2; q++) {
            __half2 sA = hz, sB = hz;
            #pragma unroll
            for (int i = 0; i < 8; i++) {
                int a  = q * 8 + i;
                int k8 = HALF16 + a;
                uint4 hv = *(const uint4*)(hsp + k8 * 4);
                __half2 h01 = *(__half2*)&hv.x, h23 = *(__half2*)&hv.y;
                __half2 h45 = *(__half2*)&hv.z, h67 = *(__half2*)&hv.w;
                uint4 wa = wregA[a], wb = wregB[a];
                sA = __hfma2(h01, *(__half2*)&wa.x, sA);
                sA = __hfma2(h23, *(__half2*)&wa.y, sA);
                sA = __hfma2(h45, *(__half2*)&wa.z, sA);
                sA = __hfma2(h67, *(__half2*)&wa.w, sA);
                sB = __hfma2(h01, *(__half2*)&wb.x, sB);
                sB = __hfma2(h23, *(__half2*)&wb.y, sB);
                sB = __hfma2(h45, *(__half2*)&wb.z, sB);
                sB = __hfma2(h67, *(__half2*)&wb.w, sB);
            }
            float2 fa = __half22float2(sA); accA += fa.x + fa.y;
            float2 fb = __half22float2(sB); accB += fb.x + fb.y;
        }

        // ---- wait for peer h of this step (flag spin) ----
        if (t) {
            uint32_t v;
            do {
                asm volatile("ld.acquire.cluster.shared::cta.b32 %0, [%1];"
                             : "=r"(v) : "r"(flagAddr) : "memory");
            } while ((int)v < t);
        }

        // ---- phase B: peer-k block, 8-chunk half2 groups ----
        #pragma unroll
        for (int q = 0; q < 2; q++) {
            __half2 sA = hz, sB = hz;
            #pragma unroll
            for (int i = 0; i < 8; i++) {
                int bi = q * 8 + i;
                int k8 = PEER16 + bi;
                uint4 hv = *(const uint4*)(hsp + k8 * 4);
                __half2 h01 = *(__half2*)&hv.x, h23 = *(__half2*)&hv.y;
                __half2 h45 = *(__half2*)&hv.z, h67 = *(__half2*)&hv.w;
                uint4 wa, wb;
                if (bi < 8) { wa = wregPA[bi]; wb = wregPB[bi]; }
                else {
                    wa = w_s[(bi - 8) * 512 + tid];
                    wb = w_s[(bi - 8) * 512 + tid + 256];
                }
                sA = __hfma2(h01, *(__half2*)&wa.x, sA);
                sA = __hfma2(h23, *(__half2*)&wa.y, sA);
                sA = __hfma2(h45, *(__half2*)&wa.z, sA);
                sA = __hfma2(h67, *(__half2*)&wa.w, sA);
                sB = __hfma2(h01, *(__half2*)&wb.x, sB);
                sB = __hfma2(h23, *(__half2*)&wb.y, sB);
                sB = __hfma2(h45, *(__half2*)&wb.z, sB);
                sB = __hfma2(h67, *(__half2*)&wb.w, sB);
            }
            float2 fa = __half22float2(sA); accA += fa.x + fa.y;
            float2 fb = __half22float2(sB); accB += fb.x + fb.y;
        }

        // ---- branch-free redundant activation tail ----
        float ga = tanh_f(accA);
        float gb = tanh_f(accB);
        float gax = __shfl_xor_sync(0xffffffffu, ga, 1);
        float gbx = __shfl_xor_sync(0xffffffffu, gb, 1);

        float ti = role ? gax : ga;
        float tf = role ? ga  : gax;
        float tg = role ? gbx : gb;
        float to = role ? gb  : gbx;

        c = c * sig_f(tf) + sig_f(ti) * tanh_f(tg);
        float hn = sig_f(to) * tanh_f(c);

        if (role)
            out[((size_t)(b * HID + half * 128 + j)) * TT + t] = hn;

        float ho = __shfl_xor_sync(0xffffffffu, hn, 2);
        if ((tid & 3) == 0) {
            __half2 hp = __floats2half2_rn(hn, ho);
            int k2 = half * 64 + (tid >> 2);
            uint32_t off = (uint32_t)(((p ^ 1) * 128 + k2) * 4);
            hs2[(p ^ 1) * 128 + k2] = hp;
            if (t + 1 < TT)
                asm volatile("st.shared::cluster.u32 [%0], %1;"
                             :: "r"(rHsBase + off), "r"(*(uint32_t*)&hp) : "memory");
        }
        __syncthreads();

        if (tid == 0 && t + 1 < TT) {
            asm volatile("fence.acq_rel.cluster;" ::: "memory");
            asm volatile("st.relaxed.cluster.shared::cluster.b32 [%0], %1;"
                         :: "r"(rFlag), "r"(t + 1) : "memory");
        }

        wxA = nxA; wxB = nxB;
    }

    if (role)
        out[(size_t)BB * HID * TT + b * HID + half * 128 + j] = c;

    asm volatile("barrier.cluster.arrive.aligned;\n\t"
                 "barrier.cluster.wait.aligned;" ::: "memory");
}

// ---------------- launch ------------------------------------------------------
extern "C" void kernel_launch(void* const* d_in, const int* in_sizes, int n_in,
                              void* d_out, int out_size) {
    const float* x   = (const float*)d_in[0];
    const float* h0  = (const float*)d_in[1];
    const float* c0  = (const float*)d_in[2];
    const float* Wih = (const float*)d_in[3];
    const float* Whh = (const float*)d_in[4];
    const float* bh  = (const float*)d_in[5];
    float* out = (float*)d_out;

    cudaFuncSetAttribute(lstm_rec_kernel,
                         cudaFuncAttributeMaxDynamicSharedMemorySize, SMEM_TOTAL_R);

    conv_whh_kernel<<<(BB * 2 * 16 * 512) / 256, 256>>>(Whh);

    wx_hmma_kernel<<<dim3(TT / 128, G4 / 128, BB), 256>>>(x, Wih, bh);

    lstm_rec_kernel<<<2 * BB, 256, SMEM_TOTAL_R>>>(h0, c0, out);

    (void)in_sizes; (void)n_in; (void)out_size;
}

// round 14
// speedup vs baseline: 1.4899x; 1.2245x over previous
#include <cuda_runtime.h>
#include <cuda_fp16.h>
#include <cstdint>
#include <math.h>

#define BB   64
#define CIN  256
#define HID  256
#define TT   512
#define G4   1024   // 4*HID

// ---------------- scratch (__device__ globals) ------------------------------
__device__ float g_wx[(size_t)TT * BB * G4];      // [t][b][col]  128 MiB
__device__ uint4 g_wA[(size_t)BB * 2 * 16 * 512]; // own-k block
__device__ uint4 g_wB[(size_t)BB * 2 * 16 * 512]; // peer-k block

// column slot lc in [0,512) -> global gate column (R10/R12 map).
__device__ __forceinline__ int gcol(int lc, int half) {
    int th   = lc & 255;
    int sel  = lc >> 8;
    int role = th & 1;
    int j    = th >> 1;
    int g    = sel * 2 + role;
    return g * 256 + half * 128 + j;
}

__device__ __forceinline__ float tanh_f(float x) {
    float e = __expf(2.0f * x);
    return 1.0f - __fdividef(2.0f, e + 1.0f);
}
__device__ __forceinline__ float sig_f(float x) {
    return __fdividef(1.0f, 1.0f + __expf(-x));
}

// ---------------- conv: W_hh fp32 -> fp16 blobs ------------------------------
__global__ __launch_bounds__(256) void conv_whh_kernel(const float* __restrict__ Whh) {
    int t    = blockIdx.x * 256 + threadIdx.x;
    int lc   = t & 511;
    int k8   = (t >> 9) & 15;
    int half = (t >> 13) & 1;
    int b    = t >> 14;
    int col  = gcol(lc, half);
    {
        int kg0 = half * 128 + k8 * 8;
        const float* s = Whh + ((size_t)b * HID + kg0) * G4 + col;
        __half hx[8];
        #pragma unroll
        for (int i = 0; i < 8; i++) hx[i] = __float2half(s[(size_t)i * G4]);
        g_wA[t] = *(uint4*)hx;
    }
    {
        int kg0 = (1 - half) * 128 + k8 * 8;
        const float* s = Whh + ((size_t)b * HID + kg0) * G4 + col;
        __half hx[8];
        #pragma unroll
        for (int i = 0; i < 8; i++) hx[i] = __float2half(s[(size_t)i * G4]);
        g_wB[t] = *(uint4*)hx;
    }
}

// ---------------- phase 1: HMMA GEMM, k-major staging + ldmatrix ------------
__device__ __forceinline__ void mma16816(float* d, const uint32_t* a, const uint32_t* bf) {
    asm volatile(
        "mma.sync.aligned.m16n8k16.row.col.f32.f16.f16.f32 "
        "{%0,%1,%2,%3}, {%4,%5,%6,%7}, {%8,%9}, {%0,%1,%2,%3};"
        : "+f"(d[0]), "+f"(d[1]), "+f"(d[2]), "+f"(d[3])
        : "r"(a[0]), "r"(a[1]), "r"(a[2]), "r"(a[3]), "r"(bf[0]), "r"(bf[1]));
}

__device__ __forceinline__ void ldsm_x4_t(uint32_t* r, uint32_t saddr) {
    asm volatile(
        "ldmatrix.sync.aligned.m8n8.x4.trans.shared.b16 {%0,%1,%2,%3}, [%4];"
        : "=r"(r[0]), "=r"(r[1]), "=r"(r[2]), "=r"(r[3]) : "r"(saddr));
}

#define LDB 136   // 128 + 8 halves pad -> 272B rows, LDSM-conflict-free

__global__ __launch_bounds__(256) void wx_hmma_kernel(
    const float* __restrict__ x,     // [B][CIN][T]
    const float* __restrict__ Wih,   // [B][CIN][4H]
    const float* __restrict__ bh)    // [B][1][4H]
{
    __shared__ __half As[32 * LDB];   // [k_local][t_local]  (native layout)
    __shared__ __half Bs[32 * LDB];   // [k_local][n_local]

    const int tid  = threadIdx.x;
    const int m0   = blockIdx.x * 128;
    const int n0   = blockIdx.y * 128;
    const int b    = blockIdx.z;
    const int wid  = tid >> 5, lane = tid & 31;
    const int wm   = (wid & 1) * 64, wn = (wid >> 1) * 32;
    const int g    = lane >> 2, tig = lane & 3;

    float acc[4][4][4];
    #pragma unroll
    for (int i = 0; i < 4; i++)
        #pragma unroll
        for (int j = 0; j < 4; j++)
            #pragma unroll
            for (int r = 0; r < 4; r++) acc[i][j][r] = 0.0f;

    const float* xb = x   + (size_t)b * CIN * TT + m0;
    const float* wb = Wih + (size_t)b * CIN * G4 + n0;

    // ldmatrix address bases (lane-dependent, loop-invariant)
    const int lane7 = lane & 7;
    const int aK = ((lane >> 4) & 1) * 8 + lane7;   // A: k_off = (g8>>1)*8
    const int aT = ((lane >> 3) & 1) * 8;           // A: t_off = (g8&1)*8
    const int bK = ((lane >> 3) & 1) * 8 + lane7;   // B: k_off = (g8&1)*8
    const int bN = ((lane >> 4) & 1) * 8;           // B: n_off = (g8>>1)*8
    const uint32_t asBase = (uint32_t)__cvta_generic_to_shared(As)
                          + (uint32_t)((aK * LDB + wm + aT) * 2);
    const uint32_t bsBase = (uint32_t)__cvta_generic_to_shared(Bs)
                          + (uint32_t)((bK * LDB + wn + bN) * 2);

    // loader indices
    const int kl = tid >> 3;          // 0..31 (k row)
    const int cq = (tid & 7) * 16;    // 0,16,...,112 (col quad base, 16 cols per thread? no)
    (void)cq;

    #pragma unroll 1
    for (int kb = 0; kb < CIN; kb += 32) {
        // stage x tile [32k][128t]: contiguous, no transpose
        #pragma unroll
        for (int i = 0; i < 4; i++) {
            int idx = tid + i * 256;           // 0..1023
            int k = idx >> 5, tq = idx & 31;   // k row, t-quad
            float4 v = *(const float4*)(xb + (size_t)(kb + k) * TT + tq * 4);
            __half2 lo = __floats2half2_rn(v.x, v.y);
            __half2 hi = __floats2half2_rn(v.z, v.w);
            uint2 pk = { *(uint32_t*)&lo, *(uint32_t*)&hi };
            *(uint2*)(As + k * LDB + tq * 4) = pk;
        }
        // stage W tile [32k][128n]
        #pragma unroll
        for (int i = 0; i < 4; i++) {
            int idx = tid + i * 256;
            int k = idx >> 5, nq = idx & 31;
            float4 v = *(const float4*)(wb + (size_t)(kb + k) * G4 + nq * 4);
            __half2 lo = __floats2half2_rn(v.x, v.y);
            __half2 hi = __floats2half2_rn(v.z, v.w);
            uint2 pk = { *(uint32_t*)&lo, *(uint32_t*)&hi };
            *(uint2*)(Bs + k * LDB + nq * 4) = pk;
        }
        __syncthreads();

        #pragma unroll
        for (int ks = 0; ks < 2; ks++) {
            const uint32_t ksOff = (uint32_t)(ks * 16 * LDB * 2);
            uint32_t a[4][4], bf[4][2];
            #pragma unroll
            for (int mf = 0; mf < 4; mf++)
                ldsm_x4_t(a[mf], asBase + ksOff + (uint32_t)(mf * 16 * 2));
            #pragma unroll
            for (int nf2 = 0; nf2 < 2; nf2++) {
                uint32_t bb[4];
                ldsm_x4_t(bb, bsBase + ksOff + (uint32_t)(nf2 * 16 * 2));
                bf[2 * nf2][0]     = bb[0];
                bf[2 * nf2][1]     = bb[1];
                bf[2 * nf2 + 1][0] = bb[2];
                bf[2 * nf2 + 1][1] = bb[3];
            }
            #pragma unroll
            for (int mf = 0; mf < 4; mf++)
                #pragma unroll
                for (int nf = 0; nf < 4; nf++)
                    mma16816(acc[mf][nf], a[mf], bf[nf]);
        }
        __syncthreads();
    }

    // epilogue: add bias, write g_wx[t][b][col]
    #pragma unroll
    for (int nf = 0; nf < 4; nf++) {
        int col = n0 + wn + nf * 8 + tig * 2;
        float2 bias = *(const float2*)(bh + (size_t)b * G4 + col);
        #pragma unroll
        for (int mf = 0; mf < 4; mf++) {
            int t0 = m0 + wm + mf * 16 + g;
            float2 v0 = { acc[mf][nf][0] + bias.x, acc[mf][nf][1] + bias.y };
            float2 v1 = { acc[mf][nf][2] + bias.x, acc[mf][nf][3] + bias.y };
            *(float2*)(g_wx + ((size_t)t0 * BB + b) * G4 + col) = v0;
            *(float2*)(g_wx + ((size_t)(t0 + 8) * BB + b) * G4 + col) = v1;
        }
    }
}

// ---------------- phase 2: recurrence (R13 verbatim) ------------------------
#define SMEM_W_BYTES  (8 * 512 * 16)                  // 65536
#define SMEM_HS_OFF   SMEM_W_BYTES
#define SMEM_FLAG_OFF (SMEM_HS_OFF + 2 * 128 * 4)
#define SMEM_TOTAL_R  (SMEM_FLAG_OFF + 16)            // 66576 B

__global__ void __cluster_dims__(2, 1, 1) __launch_bounds__(256, 1)
lstm_rec_kernel(const float* __restrict__ h0,
                const float* __restrict__ c0,
                float* __restrict__ out)
{
    extern __shared__ char smem[];
    uint4*   w_s  = (uint4*)smem;                     // peer chunks 8..15
    __half2* hs2  = (__half2*)(smem + SMEM_HS_OFF);

    const int tid    = threadIdx.x;
    const int b      = blockIdx.x >> 1;
    const int half   = blockIdx.x & 1;
    const int HALF16 = half * 16;
    const int PEER16 = 16 - HALF16;
    const int role   = tid & 1;
    const int j      = tid >> 1;

    uint4 wregA[16], wregB[16], wregPA[8], wregPB[8];
    const uint4* gwa = g_wA + ((size_t)(b * 2 + half) << 13);
    #pragma unroll
    for (int a = 0; a < 16; a++) {
        wregA[a] = gwa[a * 512 + tid];
        wregB[a] = gwa[a * 512 + tid + 256];
    }
    const uint4* gwb = g_wB + ((size_t)(b * 2 + half) << 13);
    #pragma unroll
    for (int a = 0; a < 8; a++) {
        wregPA[a] = gwb[a * 512 + tid];
        wregPB[a] = gwb[a * 512 + tid + 256];
    }
    #pragma unroll
    for (int a = 8; a < 16; a++) {
        w_s[(a - 8) * 512 + tid]       = gwb[a * 512 + tid];
        w_s[(a - 8) * 512 + tid + 256] = gwb[a * 512 + tid + 256];
    }

    float c = c0[b * HID + half * 128 + j];
    if (tid < 128)
        hs2[tid] = __floats2half2_rn(h0[b * HID + 2 * tid],
                                     h0[b * HID + 2 * tid + 1]);
    if (tid == 0)
        *(volatile uint32_t*)(smem + SMEM_FLAG_OFF) = 0;
    __syncthreads();
    asm volatile("barrier.cluster.arrive.aligned;\n\t"
                 "barrier.cluster.wait.aligned;" ::: "memory");

    const uint32_t smemBase   = (uint32_t)__cvta_generic_to_shared(smem);
    const uint32_t hsAddrBase = smemBase + SMEM_HS_OFF;
    const uint32_t flagAddr   = smemBase + SMEM_FLAG_OFF;
    const uint32_t peerRank   = (uint32_t)(half ^ 1);
    uint32_t rHsBase, rFlag;
    asm volatile("mapa.shared::cluster.u32 %0, %1, %2;"
                 : "=r"(rHsBase) : "r"(hsAddrBase), "r"(peerRank));
    asm volatile("mapa.shared::cluster.u32 %0, %1, %2;"
                 : "=r"(rFlag) : "r"(flagAddr), "r"(peerRank));

    const int colA = gcol(tid, half);
    const float* wxA_ptr = g_wx + (size_t)b * G4 + colA;
    const float* wxB_ptr = wxA_ptr + 512;

    float wxA = __ldg(wxA_ptr);
    float wxB = __ldg(wxB_ptr);
    const __half2 hz = __float2half2_rn(0.0f);

    #pragma unroll 1
    for (int t = 0; t < TT; t++) {
        const int p = t & 1;

        float nxA = wxA, nxB = wxB;
        if (t + 1 < TT) {
            size_t off = (size_t)(t + 1) * (BB * G4);
            nxA = __ldg(wxA_ptr + off);
            nxB = __ldg(wxB_ptr + off);
        }

        float accA = wxA, accB = wxB;
        const __half2* hsp = hs2 + p * 128;

        #pragma unroll
        for (int q = 0; q < 2; q++) {
            __half2 sA = hz, sB = hz;
            #pragma unroll
            for (int i = 0; i < 8; i++) {
                int a  = q * 8 + i;
                int k8 = HALF16 + a;
                uint4 hv = *(const uint4*)(hsp + k8 * 4);
                __half2 h01 = *(__half2*)&hv.x, h23 = *(__half2*)&hv.y;
                __half2 h45 = *(__half2*)&hv.z, h67 = *(__half2*)&hv.w;
                uint4 wa = wregA[a], wb = wregB[a];
                sA = __hfma2(h01, *(__half2*)&wa.x, sA);
                sA = __hfma2(h23, *(__half2*)&wa.y, sA);
                sA = __hfma2(h45, *(__half2*)&wa.z, sA);
                sA = __hfma2(h67, *(__half2*)&wa.w, sA);
                sB = __hfma2(h01, *(__half2*)&wb.x, sB);
                sB = __hfma2(h23, *(__half2*)&wb.y, sB);
                sB = __hfma2(h45, *(__half2*)&wb.z, sB);
                sB = __hfma2(h67, *(__half2*)&wb.w, sB);
            }
            float2 fa = __half22float2(sA); accA += fa.x + fa.y;
            float2 fb = __half22float2(sB); accB += fb.x + fb.y;
        }

        if (t) {
            uint32_t v;
            do {
                asm volatile("ld.acquire.cluster.shared::cta.b32 %0, [%1];"
                             : "=r"(v) : "r"(flagAddr) : "memory");
            } while ((int)v < t);
        }

        #pragma unroll
        for (int q = 0; q < 2; q++) {
            __half2 sA = hz, sB = hz;
            #pragma unroll
            for (int i = 0; i < 8; i++) {
                int bi = q * 8 + i;
                int k8 = PEER16 + bi;
                uint4 hv = *(const uint4*)(hsp + k8 * 4);
                __half2 h01 = *(__half2*)&hv.x, h23 = *(__half2*)&hv.y;
                __half2 h45 = *(__half2*)&hv.z, h67 = *(__half2*)&hv.w;
                uint4 wa, wb;
                if (bi < 8) { wa = wregPA[bi]; wb = wregPB[bi]; }
                else {
                    wa = w_s[(bi - 8) * 512 + tid];
                    wb = w_s[(bi - 8) * 512 + tid + 256];
                }
                sA = __hfma2(h01, *(__half2*)&wa.x, sA);
                sA = __hfma2(h23, *(__half2*)&wa.y, sA);
                sA = __hfma2(h45, *(__half2*)&wa.z, sA);
                sA = __hfma2(h67, *(__half2*)&wa.w, sA);
                sB = __hfma2(h01, *(__half2*)&wb.x, sB);
                sB = __hfma2(h23, *(__half2*)&wb.y, sB);
                sB = __hfma2(h45, *(__half2*)&wb.z, sB);
                sB = __hfma2(h67, *(__half2*)&wb.w, sB);
            }
            float2 fa = __half22float2(sA); accA += fa.x + fa.y;
            float2 fb = __half22float2(sB); accB += fb.x + fb.y;
        }

        float ga = tanh_f(accA);
        float gb = tanh_f(accB);
        float gax = __shfl_xor_sync(0xffffffffu, ga, 1);
        float gbx = __shfl_xor_sync(0xffffffffu, gb, 1);

        float ti = role ? gax : ga;
        float tf = role ? ga  : gax;
        float tg = role ? gbx : gb;
        float to = role ? gb  : gbx;

        c = c * sig_f(tf) + sig_f(ti) * tanh_f(tg);
        float hn = sig_f(to) * tanh_f(c);

        if (role)
            out[((size_t)(b * HID + half * 128 + j)) * TT + t] = hn;

        float ho = __shfl_xor_sync(0xffffffffu, hn, 2);
        if ((tid & 3) == 0) {
            __half2 hp = __floats2half2_rn(hn, ho);
            int k2 = half * 64 + (tid >> 2);
            uint32_t off = (uint32_t)(((p ^ 1) * 128 + k2) * 4);
            hs2[(p ^ 1) * 128 + k2] = hp;
            if (t + 1 < TT)
                asm volatile("st.shared::cluster.u32 [%0], %1;"
                             :: "r"(rHsBase + off), "r"(*(uint32_t*)&hp) : "memory");
        }
        __syncthreads();

        if (tid == 0 && t + 1 < TT) {
            asm volatile("fence.acq_rel.cluster;" ::: "memory");
            asm volatile("st.relaxed.cluster.shared::cluster.b32 [%0], %1;"
                         :: "r"(rFlag), "r"(t + 1) : "memory");
        }

        wxA = nxA; wxB = nxB;
    }

    if (role)
        out[(size_t)BB * HID * TT + b * HID + half * 128 + j] = c;

    asm volatile("barrier.cluster.arrive.aligned;\n\t"
                 "barrier.cluster.wait.aligned;" ::: "memory");
}

// ---------------- launch ------------------------------------------------------
extern "C" void kernel_launch(void* const* d_in, const int* in_sizes, int n_in,
                              void* d_out, int out_size) {
    const float* x   = (const float*)d_in[0];
    const float* h0  = (const float*)d_in[1];
    const float* c0  = (const float*)d_in[2];
    const float* Wih = (const float*)d_in[3];
    const float* Whh = (const float*)d_in[4];
    const float* bh  = (const float*)d_in[5];
    float* out = (float*)d_out;

    cudaFuncSetAttribute(lstm_rec_kernel,
                         cudaFuncAttributeMaxDynamicSharedMemorySize, SMEM_TOTAL_R);

    conv_whh_kernel<<<(BB * 2 * 16 * 512) / 256, 256>>>(Whh);

    wx_hmma_kernel<<<dim3(TT / 128, G4 / 128, BB), 256>>>(x, Wih, bh);

    lstm_rec_kernel<<<2 * BB, 256, SMEM_TOTAL_R>>>(h0, c0, out);

    (void)in_sizes; (void)n_in; (void)out_size;
}

// round 15
// speedup vs baseline: 1.5801x; 1.0605x over previous
#include <cuda_runtime.h>
#include <cuda_fp16.h>
#include <cstdint>
#include <math.h>

#define BB   64
#define CIN  256
#define HID  256
#define TT   512
#define G4   1024   // 4*HID

// ---------------- scratch (__device__ globals) ------------------------------
__device__ float g_wx[(size_t)TT * BB * G4];      // [t][b][col]  128 MiB
__device__ uint4 g_wA[(size_t)BB * 2 * 16 * 512]; // own-k block
__device__ uint4 g_wB[(size_t)BB * 2 * 16 * 512]; // peer-k block

// column slot lc in [0,512) -> global gate column (R10/R12 map).
__device__ __forceinline__ int gcol(int lc, int half) {
    int th   = lc & 255;
    int sel  = lc >> 8;
    int role = th & 1;
    int j    = th >> 1;
    int g    = sel * 2 + role;
    return g * 256 + half * 128 + j;
}

// MUFU tanh.approx activations (single-instruction)
__device__ __forceinline__ float tanh_a(float x) {
    float y;
    asm("tanh.approx.f32 %0, %1;" : "=f"(y) : "f"(x));
    return y;
}
__device__ __forceinline__ float sig_a(float x) {    // sigma(x) = 0.5 + 0.5*tanh(x/2)
    return fmaf(tanh_a(0.5f * x), 0.5f, 0.5f);
}

// ---------------- conv: W_hh fp32 -> fp16 blobs ------------------------------
__global__ __launch_bounds__(256) void conv_whh_kernel(const float* __restrict__ Whh) {
    int t    = blockIdx.x * 256 + threadIdx.x;
    int lc   = t & 511;
    int k8   = (t >> 9) & 15;
    int half = (t >> 13) & 1;
    int b    = t >> 14;
    int col  = gcol(lc, half);
    {
        int kg0 = half * 128 + k8 * 8;
        const float* s = Whh + ((size_t)b * HID + kg0) * G4 + col;
        __half hx[8];
        #pragma unroll
        for (int i = 0; i < 8; i++) hx[i] = __float2half(s[(size_t)i * G4]);
        g_wA[t] = *(uint4*)hx;
    }
    {
        int kg0 = (1 - half) * 128 + k8 * 8;
        const float* s = Whh + ((size_t)b * HID + kg0) * G4 + col;
        __half hx[8];
        #pragma unroll
        for (int i = 0; i < 8; i++) hx[i] = __float2half(s[(size_t)i * G4]);
        g_wB[t] = *(uint4*)hx;
    }
}

// ---------------- phase 1: HMMA GEMM, k-major staging + ldmatrix (R14) ------
__device__ __forceinline__ void mma16816(float* d, const uint32_t* a, const uint32_t* bf) {
    asm volatile(
        "mma.sync.aligned.m16n8k16.row.col.f32.f16.f16.f32 "
        "{%0,%1,%2,%3}, {%4,%5,%6,%7}, {%8,%9}, {%0,%1,%2,%3};"
        : "+f"(d[0]), "+f"(d[1]), "+f"(d[2]), "+f"(d[3])
        : "r"(a[0]), "r"(a[1]), "r"(a[2]), "r"(a[3]), "r"(bf[0]), "r"(bf[1]));
}

__device__ __forceinline__ void ldsm_x4_t(uint32_t* r, uint32_t saddr) {
    asm volatile(
        "ldmatrix.sync.aligned.m8n8.x4.trans.shared.b16 {%0,%1,%2,%3}, [%4];"
        : "=r"(r[0]), "=r"(r[1]), "=r"(r[2]), "=r"(r[3]) : "r"(saddr));
}

#define LDB 136   // 128 + 8 halves pad -> 272B rows, LDSM-conflict-free

__global__ __launch_bounds__(256) void wx_hmma_kernel(
    const float* __restrict__ x,     // [B][CIN][T]
    const float* __restrict__ Wih,   // [B][CIN][4H]
    const float* __restrict__ bh)    // [B][1][4H]
{
    __shared__ __half As[32 * LDB];   // [k_local][t_local]
    __shared__ __half Bs[32 * LDB];   // [k_local][n_local]

    const int tid  = threadIdx.x;
    const int m0   = blockIdx.x * 128;
    const int n0   = blockIdx.y * 128;
    const int b    = blockIdx.z;
    const int wid  = tid >> 5, lane = tid & 31;
    const int wm   = (wid & 1) * 64, wn = (wid >> 1) * 32;
    const int g    = lane >> 2, tig = lane & 3;

    float acc[4][4][4];
    #pragma unroll
    for (int i = 0; i < 4; i++)
        #pragma unroll
        for (int j = 0; j < 4; j++)
            #pragma unroll
            for (int r = 0; r < 4; r++) acc[i][j][r] = 0.0f;

    const float* xb = x   + (size_t)b * CIN * TT + m0;
    const float* wb = Wih + (size_t)b * CIN * G4 + n0;

    const int lane7 = lane & 7;
    const int aK = ((lane >> 4) & 1) * 8 + lane7;
    const int aT = ((lane >> 3) & 1) * 8;
    const int bK = ((lane >> 3) & 1) * 8 + lane7;
    const int bN = ((lane >> 4) & 1) * 8;
    const uint32_t asBase = (uint32_t)__cvta_generic_to_shared(As)
                          + (uint32_t)((aK * LDB + wm + aT) * 2);
    const uint32_t bsBase = (uint32_t)__cvta_generic_to_shared(Bs)
                          + (uint32_t)((bK * LDB + wn + bN) * 2);

    #pragma unroll 1
    for (int kb = 0; kb < CIN; kb += 32) {
        #pragma unroll
        for (int i = 0; i < 4; i++) {
            int idx = tid + i * 256;
            int k = idx >> 5, tq = idx & 31;
            float4 v = *(const float4*)(xb + (size_t)(kb + k) * TT + tq * 4);
            __half2 lo = __floats2half2_rn(v.x, v.y);
            __half2 hi = __floats2half2_rn(v.z, v.w);
            uint2 pk = { *(uint32_t*)&lo, *(uint32_t*)&hi };
            *(uint2*)(As + k * LDB + tq * 4) = pk;
        }
        #pragma unroll
        for (int i = 0; i < 4; i++) {
            int idx = tid + i * 256;
            int k = idx >> 5, nq = idx & 31;
            float4 v = *(const float4*)(wb + (size_t)(kb + k) * G4 + nq * 4);
            __half2 lo = __floats2half2_rn(v.x, v.y);
            __half2 hi = __floats2half2_rn(v.z, v.w);
            uint2 pk = { *(uint32_t*)&lo, *(uint32_t*)&hi };
            *(uint2*)(Bs + k * LDB + nq * 4) = pk;
        }
        __syncthreads();

        #pragma unroll
        for (int ks = 0; ks < 2; ks++) {
            const uint32_t ksOff = (uint32_t)(ks * 16 * LDB * 2);
            uint32_t a[4][4], bf[4][2];
            #pragma unroll
            for (int mf = 0; mf < 4; mf++)
                ldsm_x4_t(a[mf], asBase + ksOff + (uint32_t)(mf * 16 * 2));
            #pragma unroll
            for (int nf2 = 0; nf2 < 2; nf2++) {
                uint32_t bb[4];
                ldsm_x4_t(bb, bsBase + ksOff + (uint32_t)(nf2 * 16 * 2));
                bf[2 * nf2][0]     = bb[0];
                bf[2 * nf2][1]     = bb[1];
                bf[2 * nf2 + 1][0] = bb[2];
                bf[2 * nf2 + 1][1] = bb[3];
            }
            #pragma unroll
            for (int mf = 0; mf < 4; mf++)
                #pragma unroll
                for (int nf = 0; nf < 4; nf++)
                    mma16816(acc[mf][nf], a[mf], bf[nf]);
        }
        __syncthreads();
    }

    #pragma unroll
    for (int nf = 0; nf < 4; nf++) {
        int col = n0 + wn + nf * 8 + tig * 2;
        float2 bias = *(const float2*)(bh + (size_t)b * G4 + col);
        #pragma unroll
        for (int mf = 0; mf < 4; mf++) {
            int t0 = m0 + wm + mf * 16 + g;
            float2 v0 = { acc[mf][nf][0] + bias.x, acc[mf][nf][1] + bias.y };
            float2 v1 = { acc[mf][nf][2] + bias.x, acc[mf][nf][3] + bias.y };
            *(float2*)(g_wx + ((size_t)t0 * BB + b) * G4 + col) = v0;
            *(float2*)(g_wx + ((size_t)(t0 + 8) * BB + b) * G4 + col) = v1;
        }
    }
}

// ---------------- phase 2: recurrence (R13 base + tanh.approx tail) ---------
#define SMEM_W_BYTES  (8 * 512 * 16)                  // 65536
#define SMEM_HS_OFF   SMEM_W_BYTES
#define SMEM_FLAG_OFF (SMEM_HS_OFF + 2 * 128 * 4)
#define SMEM_TOTAL_R  (SMEM_FLAG_OFF + 16)            // 66576 B

__global__ void __cluster_dims__(2, 1, 1) __launch_bounds__(256, 1)
lstm_rec_kernel(const float* __restrict__ h0,
                const float* __restrict__ c0,
                float* __restrict__ out)
{
    extern __shared__ char smem[];
    uint4*   w_s  = (uint4*)smem;                     // peer chunks 8..15
    __half2* hs2  = (__half2*)(smem + SMEM_HS_OFF);

    const int tid    = threadIdx.x;
    const int b      = blockIdx.x >> 1;
    const int half   = blockIdx.x & 1;
    const int HALF16 = half * 16;
    const int PEER16 = 16 - HALF16;
    const int role   = tid & 1;
    const int j      = tid >> 1;

    uint4 wregA[16], wregB[16], wregPA[8], wregPB[8];
    const uint4* gwa = g_wA + ((size_t)(b * 2 + half) << 13);
    #pragma unroll
    for (int a = 0; a < 16; a++) {
        wregA[a] = gwa[a * 512 + tid];
        wregB[a] = gwa[a * 512 + tid + 256];
    }
    const uint4* gwb = g_wB + ((size_t)(b * 2 + half) << 13);
    #pragma unroll
    for (int a = 0; a < 8; a++) {
        wregPA[a] = gwb[a * 512 + tid];
        wregPB[a] = gwb[a * 512 + tid + 256];
    }
    #pragma unroll
    for (int a = 8; a < 16; a++) {
        w_s[(a - 8) * 512 + tid]       = gwb[a * 512 + tid];
        w_s[(a - 8) * 512 + tid + 256] = gwb[a * 512 + tid + 256];
    }

    float c = c0[b * HID + half * 128 + j];
    if (tid < 128)
        hs2[tid] = __floats2half2_rn(h0[b * HID + 2 * tid],
                                     h0[b * HID + 2 * tid + 1]);
    if (tid == 0)
        *(volatile uint32_t*)(smem + SMEM_FLAG_OFF) = 0;
    __syncthreads();
    asm volatile("barrier.cluster.arrive.aligned;\n\t"
                 "barrier.cluster.wait.aligned;" ::: "memory");

    const uint32_t smemBase   = (uint32_t)__cvta_generic_to_shared(smem);
    const uint32_t hsAddrBase = smemBase + SMEM_HS_OFF;
    const uint32_t flagAddr   = smemBase + SMEM_FLAG_OFF;
    const uint32_t peerRank   = (uint32_t)(half ^ 1);
    uint32_t rHsBase, rFlag;
    asm volatile("mapa.shared::cluster.u32 %0, %1, %2;"
                 : "=r"(rHsBase) : "r"(hsAddrBase), "r"(peerRank));
    asm volatile("mapa.shared::cluster.u32 %0, %1, %2;"
                 : "=r"(rFlag) : "r"(flagAddr), "r"(peerRank));

    const int colA = gcol(tid, half);
    const float* wxA_ptr = g_wx + (size_t)b * G4 + colA;
    const float* wxB_ptr = wxA_ptr + 512;

    float wxA = __ldg(wxA_ptr);
    float wxB = __ldg(wxB_ptr);
    const __half2 hz = __float2half2_rn(0.0f);

    #pragma unroll 1
    for (int t = 0; t < TT; t++) {
        const int p = t & 1;

        float nxA = wxA, nxB = wxB;
        if (t + 1 < TT) {
            size_t off = (size_t)(t + 1) * (BB * G4);
            nxA = __ldg(wxA_ptr + off);
            nxB = __ldg(wxB_ptr + off);
        }

        float accA = wxA, accB = wxB;
        const __half2* hsp = hs2 + p * 128;

        #pragma unroll
        for (int q = 0; q < 2; q++) {
            __half2 sA = hz, sB = hz;
            #pragma unroll
            for (int i = 0; i < 8; i++) {
                int a  = q * 8 + i;
                int k8 = HALF16 + a;
                uint4 hv = *(const uint4*)(hsp + k8 * 4);
                __half2 h01 = *(__half2*)&hv.x, h23 = *(__half2*)&hv.y;
                __half2 h45 = *(__half2*)&hv.z, h67 = *(__half2*)&hv.w;
                uint4 wa = wregA[a], wb = wregB[a];
                sA = __hfma2(h01, *(__half2*)&wa.x, sA);
                sA = __hfma2(h23, *(__half2*)&wa.y, sA);
                sA = __hfma2(h45, *(__half2*)&wa.z, sA);
                sA = __hfma2(h67, *(__half2*)&wa.w, sA);
                sB = __hfma2(h01, *(__half2*)&wb.x, sB);
                sB = __hfma2(h23, *(__half2*)&wb.y, sB);
                sB = __hfma2(h45, *(__half2*)&wb.z, sB);
                sB = __hfma2(h67, *(__half2*)&wb.w, sB);
            }
            float2 fa = __half22float2(sA); accA += fa.x + fa.y;
            float2 fb = __half22float2(sB); accB += fb.x + fb.y;
        }

        if (t) {
            uint32_t v;
            do {
                asm volatile("ld.acquire.cluster.shared::cta.b32 %0, [%1];"
                             : "=r"(v) : "r"(flagAddr) : "memory");
            } while ((int)v < t);
        }

        #pragma unroll
        for (int q = 0; q < 2; q++) {
            __half2 sA = hz, sB = hz;
            #pragma unroll
            for (int i = 0; i < 8; i++) {
                int bi = q * 8 + i;
                int k8 = PEER16 + bi;
                uint4 hv = *(const uint4*)(hsp + k8 * 4);
                __half2 h01 = *(__half2*)&hv.x, h23 = *(__half2*)&hv.y;
                __half2 h45 = *(__half2*)&hv.z, h67 = *(__half2*)&hv.w;
                uint4 wa, wb;
                if (bi < 8) { wa = wregPA[bi]; wb = wregPB[bi]; }
                else {
                    wa = w_s[(bi - 8) * 512 + tid];
                    wb = w_s[(bi - 8) * 512 + tid + 256];
                }
                sA = __hfma2(h01, *(__half2*)&wa.x, sA);
                sA = __hfma2(h23, *(__half2*)&wa.y, sA);
                sA = __hfma2(h45, *(__half2*)&wa.z, sA);
                sA = __hfma2(h67, *(__half2*)&wa.w, sA);
                sB = __hfma2(h01, *(__half2*)&wb.x, sB);
                sB = __hfma2(h23, *(__half2*)&wb.y, sB);
                sB = __hfma2(h45, *(__half2*)&wb.z, sB);
                sB = __hfma2(h67, *(__half2*)&wb.w, sB);
            }
            float2 fa = __half22float2(sA); accA += fa.x + fa.y;
            float2 fb = __half22float2(sB); accB += fb.x + fb.y;
        }

        // ---- tail with MUFU tanh.approx ----
        float ga = tanh_a(accA);
        float gb = tanh_a(accB);
        float gax = __shfl_xor_sync(0xffffffffu, ga, 1);
        float gbx = __shfl_xor_sync(0xffffffffu, gb, 1);

        float ti = role ? gax : ga;
        float tf = role ? ga  : gax;
        float tg = role ? gbx : gb;
        float to = role ? gb  : gbx;

        c = c * sig_a(tf) + sig_a(ti) * tanh_a(tg);
        float hn = sig_a(to) * tanh_a(c);

        if (role)
            out[((size_t)(b * HID + half * 128 + j)) * TT + t] = hn;

        float ho = __shfl_xor_sync(0xffffffffu, hn, 2);
        if ((tid & 3) == 0) {
            __half2 hp = __floats2half2_rn(hn, ho);
            int k2 = half * 64 + (tid >> 2);
            uint32_t off = (uint32_t)(((p ^ 1) * 128 + k2) * 4);
            hs2[(p ^ 1) * 128 + k2] = hp;
            if (t + 1 < TT)
                asm volatile("st.shared::cluster.u32 [%0], %1;"
                             :: "r"(rHsBase + off), "r"(*(uint32_t*)&hp) : "memory");
        }
        __syncthreads();

        if (tid == 0 && t + 1 < TT) {
            asm volatile("fence.acq_rel.cluster;" ::: "memory");
            asm volatile("st.relaxed.cluster.shared::cluster.b32 [%0], %1;"
                         :: "r"(rFlag), "r"(t + 1) : "memory");
        }

        wxA = nxA; wxB = nxB;
    }

    if (role)
        out[(size_t)BB * HID * TT + b * HID + half * 128 + j] = c;

    asm volatile("barrier.cluster.arrive.aligned;\n\t"
                 "barrier.cluster.wait.aligned;" ::: "memory");
}

// ---------------- launch ------------------------------------------------------
extern "C" void kernel_launch(void* const* d_in, const int* in_sizes, int n_in,
                              void* d_out, int out_size) {
    const float* x   = (const float*)d_in[0];
    const float* h0  = (const float*)d_in[1];
    const float* c0  = (const float*)d_in[2];
    const float* Wih = (const float*)d_in[3];
    const float* Whh = (const float*)d_in[4];
    const float* bh  = (const float*)d_in[5];
    float* out = (float*)d_out;

    cudaFuncSetAttribute(lstm_rec_kernel,
                         cudaFuncAttributeMaxDynamicSharedMemorySize, SMEM_TOTAL_R);

    conv_whh_kernel<<<(BB * 2 * 16 * 512) / 256, 256>>>(Whh);

    wx_hmma_kernel<<<dim3(TT / 128, G4 / 128, BB), 256>>>(x, Wih, bh);

    lstm_rec_kernel<<<2 * BB, 256, SMEM_TOTAL_R>>>(h0, c0, out);

    (void)in_sizes; (void)n_in; (void)out_size;
}